// round 17
// baseline (speedup 1.0000x reference)
#include <cuda_runtime.h>
#include <cuda_fp16.h>
#include <cstdint>

#define T_ 7
#define NTOK 36864            // B*H*W
#define ROWS (T_ * NTOK)      // 258048
#define CDIM 256
#define NQKV 768
#define NCTA 296              // 2 CTAs x 148 SMs
#define RB_TOT 2016           // ROWS/128

// Scratch (device globals — no allocation allowed)
__device__ __half g_qkv_h[(size_t)ROWS * NQKV];  // [t*NTOK+s][q|k|v], fp16
__device__ __half g_ctx_h[(size_t)ROWS * CDIM];  // attn out, fp16
__device__ __half g_wbt_h[NQKV * CDIM];          // [n][k], fp16
__device__ __half g_wot_h[CDIM * CDIM];          // [c][nd], fp16
__device__ float  g_bias[T_ * NQKV];

// ---------------------------------------------------------------------------
// Portable PTX helpers (compute_103 virtual arch — no tcgen05/TMA-tensor)
// ---------------------------------------------------------------------------
__device__ __forceinline__ uint32_t smem_u32(const void* p) {
    uint32_t a;
    asm("{ .reg .u64 t; cvta.to.shared.u64 t, %1; cvt.u32.u64 %0, t; }" : "=r"(a) : "l"(p));
    return a;
}
__device__ __forceinline__ void ldsm4(uint32_t* r, uint32_t addr) {
    asm volatile("ldmatrix.sync.aligned.m8n8.x4.shared.b16 {%0,%1,%2,%3}, [%4];"
        : "=r"(r[0]), "=r"(r[1]), "=r"(r[2]), "=r"(r[3]) : "r"(addr));
}
__device__ __forceinline__ void mma_f16(float* d, const uint32_t* a, const uint32_t* b) {
    asm volatile("mma.sync.aligned.m16n8k16.row.col.f32.f16.f16.f32 "
        "{%0,%1,%2,%3}, {%4,%5,%6,%7}, {%8,%9}, {%0,%1,%2,%3};"
        : "+f"(d[0]), "+f"(d[1]), "+f"(d[2]), "+f"(d[3])
        : "r"(a[0]), "r"(a[1]), "r"(a[2]), "r"(a[3]), "r"(b[0]), "r"(b[1]));
}
#define CP_ASYNC16(dst, src) asm volatile("cp.async.cg.shared.global [%0], [%1], 16;" :: "r"(dst), "l"(src))
#define CP_COMMIT()          asm volatile("cp.async.commit_group;" ::: "memory")
#define CP_WAIT1()           asm volatile("cp.async.wait_group 1;" ::: "memory")

__device__ __forceinline__ uint2 f4_to_h4(float4 v) {
    __half2 h0 = __float22half2_rn(make_float2(v.x, v.y));
    __half2 h1 = __float22half2_rn(make_float2(v.z, v.w));
    uint2 r;
    r.x = *reinterpret_cast<uint32_t*>(&h0);
    r.y = *reinterpret_cast<uint32_t*>(&h1);
    return r;
}
__device__ __forceinline__ float4 h4_to_f4(uint2 u) {
    __half2 h0 = *reinterpret_cast<__half2*>(&u.x);
    __half2 h1 = *reinterpret_cast<__half2*>(&u.y);
    float2 a = __half22float2(h0), b = __half22float2(h1);
    return make_float4(a.x, a.y, b.x, b.y);
}

#define STAGE_BYTES 32768u            // GEMM2: A 16KB + B 16KB per ring slot
#define SM_TOTAL_G2 (3 * STAGE_BYTES) // 96KB/CTA -> 2 CTAs/SM

// GEMM1: resident A tile (4 chunks x 16KB = 64KB) + B ring (3 x 16KB)
#define SM_A1 65536u
#define SM_TOTAL_G1 (SM_A1 + 3 * 16384u)   // 112KB/CTA -> 2 CTAs/SM (224KB)

// ---------------------------------------------------------------------------
// Prep: weights pack+transpose, t_emb-folded bias (frames conversion now
// lives inside GEMM1's per-row-block prologue).
// ---------------------------------------------------------------------------
#define NBLK_WT   1024        // (NQKV*CDIM + CDIM*CDIM)/256
#define NBLK_BIAS 21          // ceil(T_*NQKV/256)

__global__ void prep_kernel(const float* __restrict__ te,
                            const float* __restrict__ Wq,
                            const float* __restrict__ bq,
                            const float* __restrict__ Wk,
                            const float* __restrict__ bk,
                            const float* __restrict__ Wv,
                            const float* __restrict__ bv,
                            const float* __restrict__ Wo) {
    const int bid = blockIdx.x;
    if (bid < NBLK_WT) {
        int i = bid * 256 + threadIdx.x;
        if (i < NQKV * CDIM) {
            int n = i / CDIM, c = i % CDIM;
            float v;
            if (n < 256)      v = Wq[c * 256 + n];
            else if (n < 512) v = Wk[c * 256 + (n - 256)];
            else              v = Wv[c * 256 + (n - 512)];
            g_wbt_h[i] = __float2half_rn(v);
        } else {
            int j = i - NQKV * CDIM;
            int co = j / CDIM, nd = j % CDIM;
            g_wot_h[j] = __float2half_rn(Wo[nd * 256 + co]);
        }
    } else {
        int i = (bid - NBLK_WT) * 256 + threadIdx.x;
        if (i >= T_ * NQKV) return;
        int t = i / NQKV, n = i % NQKV;
        float r;
        if (n < 512) {
            const float* W = (n < 256) ? Wq : Wk;
            int nn = n & 255;
            float acc = (n < 256) ? bq[nn] : bk[nn];
            for (int c = 0; c < CDIM; c++) acc += te[t * CDIM + c] * W[c * 256 + nn];
            r = acc;
        } else {
            r = bv[n - 512];
        }
        g_bias[i] = r;
    }
}

// ---------------------------------------------------------------------------
// GEMM1 (fused frames conversion): persistent, CTA owns whole row-blocks.
// Per row-block rb: convert A (128x256 f32 -> fp16, once) into a resident
// 64KB smem tile, then run 6 col-tiles (N=128 each) with B streaming through
// a 3-slot ring (global chunk stream gl: rb-iter*24 + col*4 + kc).
// Epilogue per col-tile: acc+bias -> fp16 in regs, 4 passes x 32 rows staged
// [32][136] fp16 (8.7KB) in the free ring slot. 8 warps, warp tile 32x64.
// ---------------------------------------------------------------------------
__global__ __launch_bounds__(256, 2)
void gemm1_kernel(const float* __restrict__ frames,
                  const __half* __restrict__ Bt,
                  const float* __restrict__ bias,
                  __half* __restrict__ Cout) {
    extern __shared__ __align__(128) char smem[];
    const uint32_t sb = smem_u32(smem);          // A tile (4 x 16KB)
    const uint32_t smB = sb + SM_A1;             // B ring

    const int tid  = threadIdx.x;
    const int lane = tid & 31, wid = tid >> 5;
    const int wm = wid >> 1;          // 0..3 : rows wm*32
    const int wn = wid & 1;           // 0..1 : cols wn*64
    const int cblk = blockIdx.x;

    const uint32_t fxor  = (uint32_t)(lane & 7) << 4;
    const uint32_t a_row = (uint32_t)(wm * 32 + (lane & 15)) * 128;
    const uint32_t ahalf = (uint32_t)(lane >> 4) * 16;
    const uint32_t b_row = (uint32_t)(wn * 64 + (lane & 7) + ((lane >> 4) << 3)) * 128;
    const uint32_t bhalf = (uint32_t)((lane >> 3) & 1) * 16;

    // Stage B chunk for global stream id gl2: rb = cblk + (gl2/24)*NCTA,
    // col = (gl2%24)>>2, kc = gl2&3. Slot = gl2%3. Commit unconditionally.
    auto stageB = [&](int gl2) {
        const int rbi = cblk + (gl2 / 24) * NCTA;
        if (rbi < RB_TOT) {
            const int rem = gl2 % 24;
            const int col = rem >> 2, kc = rem & 3;
            const uint32_t nb = smB + (uint32_t)(gl2 % 3) * 16384u;
            #pragma unroll
            for (int i = 0; i < 4; i++) {
                int g = tid + i * 256;             // 1024 granules: 128 rows x 8
                int r = g >> 3, c16 = g & 7;
                uint32_t dst = nb + (uint32_t)r * 128 + (((uint32_t)c16 * 16) ^ (((uint32_t)(r & 7)) << 4));
                CP_ASYNC16(dst, Bt + (size_t)(col * 128 + r) * CDIM + kc * 64 + c16 * 8);
            }
        }
        CP_COMMIT();
    };

    stageB(0);
    stageB(1);

    int gl = 0;
    #pragma unroll 1
    for (int rb = cblk; rb < RB_TOT; rb += NCTA) {
        const int row0 = rb * 128;
        const int t = rb / 288;

        // ---- convert A row-block: f32 -> fp16 into resident swizzled tile ----
        // (previous row-block's compute + epilogue fully synced; ring cps are
        //  to a different smem region.)
        #pragma unroll 4
        for (int i = 0; i < 16; i++) {
            int g = tid + i * 256;                 // 4096 granules: 128 rows x 32
            int r = g >> 5, c8 = g & 31;           // c8: 8-f32 group
            const float4* src = reinterpret_cast<const float4*>(
                frames + (size_t)(row0 + r) * CDIM + c8 * 8);
            float4 v0 = src[0], v1 = src[1];
            uint2 h0 = f4_to_h4(v0), h1 = f4_to_h4(v1);
            uint32_t dst = sb + (uint32_t)(c8 >> 3) * 16384u + (uint32_t)r * 128
                         + ((((uint32_t)(c8 & 7)) * 16u) ^ (((uint32_t)(r & 7)) << 4));
            asm volatile("st.shared.v4.b32 [%0], {%1,%2,%3,%4};"
                :: "r"(dst), "r"(h0.x), "r"(h0.y), "r"(h1.x), "r"(h1.y));
        }
        __syncthreads();   // A tile visible to all warps

        #pragma unroll 1
        for (int col = 0; col < 6; col++) {
            const int col0 = col * 128;

            float acc[2][8][4];
            #pragma unroll
            for (int mt = 0; mt < 2; mt++)
                #pragma unroll
                for (int nt = 0; nt < 8; nt++)
                    #pragma unroll
                    for (int e = 0; e < 4; e++) acc[mt][nt][e] = 0.0f;

            #pragma unroll 1
            for (int kc = 0; kc < 4; kc++, gl++) {
                const uint32_t aBase = sb + (uint32_t)kc * 16384u;
                const uint32_t bBase = smB + (uint32_t)(gl % 3) * 16384u;
                CP_WAIT1();
                __syncthreads();
                stageB(gl + 2);

                #pragma unroll
                for (int ks = 0; ks < 4; ks++) {
                    uint32_t af[2][4];
                    #pragma unroll
                    for (int mt = 0; mt < 2; mt++)
                        ldsm4(af[mt], aBase + a_row + (uint32_t)mt * 2048 + ((ahalf + ks * 32) ^ fxor));
                    uint32_t bf[4][4];
                    #pragma unroll
                    for (int np = 0; np < 4; np++)
                        ldsm4(bf[np], bBase + b_row + (uint32_t)np * 2048 + ((bhalf + ks * 32) ^ fxor));
                    #pragma unroll
                    for (int mt = 0; mt < 2; mt++)
                        #pragma unroll
                        for (int nt = 0; nt < 8; nt++)
                            mma_f16(acc[mt][nt], af[mt], &bf[nt >> 1][(nt & 1) * 2]);
                }
            }
            __syncthreads();   // reads of the freed ring slot done

            // ---- epilogue: fp16 in regs, 4 passes of 32 rows in free slot ----
            __half* Hs = reinterpret_cast<__half*>(smem + SM_A1 + (size_t)((gl + 2) % 3) * 16384u);
            float2 br[8];
            #pragma unroll
            for (int nt = 0; nt < 8; nt++)
                br[nt] = *reinterpret_cast<const float2*>(
                    bias + t * NQKV + col0 + wn * 64 + nt * 8 + (lane & 3) * 2);

            #pragma unroll 1
            for (int p = 0; p < 4; p++) {
                if (wm == p) {
                    #pragma unroll
                    for (int mt = 0; mt < 2; mt++) {
                        const int lr = mt * 16 + (lane >> 2);
                        #pragma unroll
                        for (int nt = 0; nt < 8; nt++) {
                            const int c0 = wn * 64 + nt * 8 + (lane & 3) * 2;
                            __half2 v0 = __float22half2_rn(make_float2(acc[mt][nt][0] + br[nt].x,
                                                                       acc[mt][nt][1] + br[nt].y));
                            __half2 v1 = __float22half2_rn(make_float2(acc[mt][nt][2] + br[nt].x,
                                                                       acc[mt][nt][3] + br[nt].y));
                            *reinterpret_cast<__half2*>(Hs + lr * 136 + c0)       = v0;
                            *reinterpret_cast<__half2*>(Hs + (lr + 8) * 136 + c0) = v1;
                        }
                    }
                }
                __syncthreads();
                #pragma unroll
                for (int i = 0; i < 2; i++) {
                    int id = tid + i * 256;          // 512 slots: 32 rows x 16 uint4
                    int r = id >> 4, c8 = id & 15;
                    uint4 v = *reinterpret_cast<const uint4*>(Hs + r * 136 + c8 * 8);
                    *reinterpret_cast<uint4*>(Cout + (size_t)(row0 + p * 32 + r) * NQKV + col0 + c8 * 8) = v;
                }
                __syncthreads();
            }
        }
    }
}

// ---------------------------------------------------------------------------
// Persistent GEMM2 (R16/R12-proven): f32 out, 4-pass f32 epilogue.
// ---------------------------------------------------------------------------
template<int NB, int TSTRIDE>
__global__ __launch_bounds__(256, 2)
void gemm_persist_kernel(const __half* __restrict__ A,
                         const __half* __restrict__ Bt,
                         const float* __restrict__ bias,
                         float* __restrict__ Cout) {
    extern __shared__ __align__(128) char smem[];
    const uint32_t sb = smem_u32(smem);
    const int NWIDTH = NB * 128;
    const int ntiles = NB * (ROWS / 128);

    const int tid  = threadIdx.x;
    const int lane = tid & 31, wid = tid >> 5;
    const int wm = wid >> 1;
    const int wn = wid & 1;
    const int cblk = blockIdx.x;

    const uint32_t fxor  = (uint32_t)(lane & 7) << 4;
    const uint32_t a_row = (uint32_t)(wm * 32 + (lane & 15)) * 128;
    const uint32_t ahalf = (uint32_t)(lane >> 4) * 16;
    const uint32_t b_row = (uint32_t)(wn * 64 + (lane & 7) + ((lane >> 4) << 3)) * 128;
    const uint32_t bhalf = (uint32_t)((lane >> 3) & 1) * 16;

    auto stageG = [&](int gl) {
        const int tt = cblk + (gl >> 2) * NCTA;
        if (tt < ntiles) {
            const int kc = gl & 3;
            const int r0 = (tt / NB) * 128;
            const int c0 = (tt % NB) * 128;
            const uint32_t nb = sb + (uint32_t)(gl % 3) * STAGE_BYTES;
            #pragma unroll
            for (int i = 0; i < 4; i++) {
                int g = tid + i * 256;
                int r = g >> 3, c16 = g & 7;
                uint32_t dst = nb + (uint32_t)r * 128 + (((uint32_t)c16 * 16) ^ (((uint32_t)(r & 7)) << 4));
                CP_ASYNC16(dst, A + (size_t)(r0 + r) * CDIM + kc * 64 + c16 * 8);
            }
            #pragma unroll
            for (int i = 0; i < 4; i++) {
                int g = tid + i * 256;
                int r = g >> 3, c16 = g & 7;
                uint32_t dst = nb + 16384u + (uint32_t)r * 128 + (((uint32_t)c16 * 16) ^ (((uint32_t)(r & 7)) << 4));
                CP_ASYNC16(dst, Bt + (size_t)(c0 + r) * CDIM + kc * 64 + c16 * 8);
            }
        }
        CP_COMMIT();
    };

    stageG(0);
    stageG(1);

    int gl = 0;
    #pragma unroll 1
    for (int tau = cblk; tau < ntiles; tau += NCTA) {
        const int rowblk = tau / NB;
        const int row0 = rowblk * 128;
        const int col0 = (tau % NB) * 128;

        float acc[2][8][4];
        #pragma unroll
        for (int mt = 0; mt < 2; mt++)
            #pragma unroll
            for (int nt = 0; nt < 8; nt++)
                #pragma unroll
                for (int e = 0; e < 4; e++) acc[mt][nt][e] = 0.0f;

        #pragma unroll 1
        for (int kc = 0; kc < 4; kc++, gl++) {
            const uint32_t base = sb + (uint32_t)(gl % 3) * STAGE_BYTES;
            CP_WAIT1();
            __syncthreads();
            stageG(gl + 2);

            #pragma unroll
            for (int ks = 0; ks < 4; ks++) {
                uint32_t af[2][4];
                #pragma unroll
                for (int mt = 0; mt < 2; mt++)
                    ldsm4(af[mt], base + a_row + (uint32_t)mt * 2048 + ((ahalf + ks * 32) ^ fxor));
                uint32_t bf[4][4];
                #pragma unroll
                for (int np = 0; np < 4; np++)
                    ldsm4(bf[np], base + 16384u + b_row + (uint32_t)np * 2048 + ((bhalf + ks * 32) ^ fxor));
                #pragma unroll
                for (int mt = 0; mt < 2; mt++)
                    #pragma unroll
                    for (int nt = 0; nt < 8; nt++)
                        mma_f16(acc[mt][nt], af[mt], &bf[nt >> 1][(nt & 1) * 2]);
            }
        }
        __syncthreads();

        float* Cs = reinterpret_cast<float*>(smem + (size_t)((gl + 2) % 3) * STAGE_BYTES);
        const int t = TSTRIDE ? (rowblk / 288) : 0;
        float2 br[8];
        #pragma unroll
        for (int nt = 0; nt < 8; nt++)
            br[nt] = *reinterpret_cast<const float2*>(
                bias + t * TSTRIDE + col0 + wn * 64 + nt * 8 + (lane & 3) * 2);

        #pragma unroll 1
        for (int p = 0; p < 4; p++) {
            if (wm == p) {
                #pragma unroll
                for (int mt = 0; mt < 2; mt++) {
                    const int r0 = mt * 16 + (lane >> 2);
                    #pragma unroll
                    for (int nt = 0; nt < 8; nt++) {
                        const int c0 = wn * 64 + nt * 8 + (lane & 3) * 2;
                        *reinterpret_cast<float2*>(Cs + r0 * 132 + c0) =
                            make_float2(acc[mt][nt][0] + br[nt].x, acc[mt][nt][1] + br[nt].y);
                        *reinterpret_cast<float2*>(Cs + (r0 + 8) * 132 + c0) =
                            make_float2(acc[mt][nt][2] + br[nt].x, acc[mt][nt][3] + br[nt].y);
                    }
                }
            }
            __syncthreads();
            #pragma unroll
            for (int i = 0; i < 4; i++) {
                int id = tid + i * 256;
                int r = id >> 5, c = (id & 31) * 4;
                float4 v = *reinterpret_cast<const float4*>(Cs + r * 132 + c);
                *reinterpret_cast<float4*>(Cout + (size_t)(row0 + p * 32 + r) * NWIDTH + col0 + c) = v;
            }
            __syncthreads();
        }
    }
}

// ---------------------------------------------------------------------------
// Attention over T=7 per (token, 4-head group), fp16 in / fp16 out.
// K/V stay packed fp16 (uint2), converted once per t (R14-proven).
// ---------------------------------------------------------------------------
__global__ void attn_kernel() {
    const int gw = (blockIdx.x * blockDim.x + threadIdx.x) >> 5;
    const int lane = threadIdx.x & 31;
    const int s = gw >> 1;
    const int half = gw & 1;
    const int hg = lane >> 3, dg = lane & 7;
    const int col = (half * 4 + hg) * 32 + dg * 4;

    float4 q[7];
    uint2 kp[7], vp[7];
    #pragma unroll
    for (int t = 0; t < 7; t++) {
        const __half* base = g_qkv_h + (size_t)(t * NTOK + s) * NQKV;
        q[t]  = h4_to_f4(*reinterpret_cast<const uint2*>(base + col));
        kp[t] = *reinterpret_cast<const uint2*>(base + 256 + col);
        vp[t] = *reinterpret_cast<const uint2*>(base + 512 + col);
    }

    const float scale = 0.17677669529663687f;  // 1/sqrt(32)
    float e[7] = {0.f, 0.f, 0.f, 0.f, 0.f, 0.f, 0.f};
    #pragma unroll
    for (int t = 0; t < 7; t++) {
        const float4 kf = h4_to_f4(kp[t]);
        #pragma unroll
        for (int qt = 0; qt < 7; qt++) {
            float d = q[qt].x * kf.x + q[qt].y * kf.y
                    + q[qt].z * kf.z + q[qt].w * kf.w;
            d += __shfl_xor_sync(0xffffffffu, d, 1);
            d += __shfl_xor_sync(0xffffffffu, d, 2);
            d += __shfl_xor_sync(0xffffffffu, d, 4);
            const int p = qt * 7 + t;
            if ((p & 7) == dg) e[p >> 3] = __expf(d * scale);
        }
    }

    float4 ctx[7];
    float den[7];
    #pragma unroll
    for (int qt = 0; qt < 7; qt++) { ctx[qt] = make_float4(0, 0, 0, 0); den[qt] = 0.f; }
    #pragma unroll
    for (int t = 0; t < 7; t++) {
        const float4 vf = h4_to_f4(vp[t]);
        #pragma unroll
        for (int qt = 0; qt < 7; qt++) {
            const int p = qt * 7 + t;
            float eb = __shfl_sync(0xffffffffu, e[p >> 3], p & 7, 8);
            den[qt] += eb;
            ctx[qt].x += eb * vf.x;
            ctx[qt].y += eb * vf.y;
            ctx[qt].z += eb * vf.z;
            ctx[qt].w += eb * vf.w;
        }
    }
    #pragma unroll
    for (int qt = 0; qt < 7; qt++) {
        const float r = 1.0f / den[qt];
        float4 o = make_float4(ctx[qt].x * r, ctx[qt].y * r, ctx[qt].z * r, ctx[qt].w * r);
        *reinterpret_cast<uint2*>(g_ctx_h + (size_t)(qt * NTOK + s) * CDIM + col) = f4_to_h4(o);
    }
}

// ---------------------------------------------------------------------------
extern "C" void kernel_launch(void* const* d_in, const int* /*in_sizes*/, int /*n_in*/,
                              void* d_out, int /*out_size*/) {
    const float* frames = (const float*)d_in[0];
    const float* temb   = (const float*)d_in[1];
    const float* Wq     = (const float*)d_in[2];
    const float* bq     = (const float*)d_in[3];
    const float* Wk     = (const float*)d_in[4];
    const float* bk     = (const float*)d_in[5];
    const float* Wv     = (const float*)d_in[6];
    const float* bv     = (const float*)d_in[7];
    const float* Wo     = (const float*)d_in[8];
    const float* bo     = (const float*)d_in[9];
    float* out = (float*)d_out;

    void *p_qkv, *p_ctx, *p_wbt, *p_wot, *p_bias;
    cudaGetSymbolAddress(&p_qkv,  g_qkv_h);
    cudaGetSymbolAddress(&p_ctx,  g_ctx_h);
    cudaGetSymbolAddress(&p_wbt,  g_wbt_h);
    cudaGetSymbolAddress(&p_wot,  g_wot_h);
    cudaGetSymbolAddress(&p_bias, g_bias);

    cudaFuncSetAttribute(gemm1_kernel,
                         cudaFuncAttributeMaxDynamicSharedMemorySize, SM_TOTAL_G1);
    cudaFuncSetAttribute(gemm_persist_kernel<2, 0>,
                         cudaFuncAttributeMaxDynamicSharedMemorySize, SM_TOTAL_G2);

    // Prep: weight pack + bias fold only
    prep_kernel<<<NBLK_WT + NBLK_BIAS, 256>>>(temb, Wq, bq, Wk, bk, Wv, bv, Wo);

    // QKV projection (fused frames->fp16 conversion): frames @ Wbt + bias[t]
    gemm1_kernel<<<NCTA, 256, SM_TOTAL_G1>>>(
        frames, (const __half*)p_wbt, (const float*)p_bias, (__half*)p_qkv);

    // Attention (fp16 -> fp16)
    attn_kernel<<<(NTOK * 2 * 32) / 256, 256>>>();

    // Output projection (persistent): ctx @ Wot + bo -> f32
    gemm_persist_kernel<2, 0><<<NCTA, 256, SM_TOTAL_G2>>>(
        (const __half*)p_ctx, (const __half*)p_wot, bo, (float*)out);
}